// round 5
// baseline (speedup 1.0000x reference)
#include <cuda_runtime.h>
#include <float.h>

// SOM2D winner-take-all, GB300 sm_103a.
// d = (||x||^2 + ||w||^2) - 2*x.w, matching the reference's fp32 expression
// structure (separate add/mul/sub, no fma contraction on the combine).
// Output written as FLOAT32 label values (harness metric compares floats).
//
// Static smem only (42.2 KB), no attribute calls, no dynamic smem.
// X tile 64x132 (float4 LDS conflict-free), W tile 16x132 register-prefetched.
// ||w||^2 precomputed by a helper kernel into a __device__ global.

#define DD   128
#define TN   64     // samples per block
#define TM   16     // units per tile
#define XSTR 132
#define WSTR 132

__device__ float g_wsq[8192];

__global__ void wsq_kernel(const float* __restrict__ W, int M)
{
    int m = blockIdx.x * blockDim.x + threadIdx.x;
    if (m < M) {
        const float* row = W + (size_t)m * DD;
        float s = 0.f;
#pragma unroll 8
        for (int k = 0; k < DD; k++) s = fmaf(row[k], row[k], s);
        g_wsq[m] = s;
    }
}

__global__ __launch_bounds__(256)
void som_kernel(const float* __restrict__ X, const float* __restrict__ W,
                const int* __restrict__ grid, float* __restrict__ out,
                int N, int M)
{
    __shared__ float X_s[TN * XSTR];   // 33792 B
    __shared__ float W_s[TM * WSTR];   //  8448 B

    const int tid = threadIdx.x;
    const int tx  = tid & 15;          // unit lane within tile
    const int ty  = tid >> 4;          // sample lane
    const int n0  = blockIdx.x * TN;

    // ---- load X tile [TN x DD], float4 coalesced ----
    for (int i = tid; i < TN * 32; i += 256) {
        int r = i >> 5, c = i & 31;
        float4 v = (n0 + r < N)
                 ? reinterpret_cast<const float4*>(X + (size_t)(n0 + r) * DD)[c]
                 : make_float4(0.f, 0.f, 0.f, 0.f);
        *reinterpret_cast<float4*>(&X_s[r * XSTR + 4 * c]) = v;
    }
    __syncthreads();

    // ---- per-row ||x||^2 for this thread's 4 sample rows ----
    float xq[4];
#pragma unroll
    for (int i = 0; i < 4; i++) {
        const float* xr = &X_s[(ty + 16 * i) * XSTR];
        float s = 0.f;
#pragma unroll 8
        for (int k = 0; k < DD; k++) s = fmaf(xr[k], xr[k], s);
        xq[i] = s;
    }

    // ---- prefetch W tile 0 into registers (512 float4, 2/thread) ----
    const int r0 = tid >> 5, c0 = tid & 31;
    const int r1 = (tid + 256) >> 5, c1 = tid & 31;
    float4 pre0 = reinterpret_cast<const float4*>(W + (size_t)r0 * DD)[c0];
    float4 pre1 = reinterpret_cast<const float4*>(W + (size_t)r1 * DD)[c1];

    float bv[4];
    int   bi[4];
#pragma unroll
    for (int i = 0; i < 4; i++) { bv[i] = FLT_MAX; bi[i] = 0; }

    const int nt = M / TM;
    for (int t = 0; t < nt; t++) {
        *reinterpret_cast<float4*>(&W_s[r0 * WSTR + 4 * c0]) = pre0;
        *reinterpret_cast<float4*>(&W_s[r1 * WSTR + 4 * c1]) = pre1;
        __syncthreads();

        if (t + 1 < nt) {
            int base = (t + 1) * TM;
            pre0 = reinterpret_cast<const float4*>(W + (size_t)(base + r0) * DD)[c0];
            pre1 = reinterpret_cast<const float4*>(W + (size_t)(base + r1) * DD)[c1];
        }

        // ---- dot products: 4 sample rows x 1 unit column per thread ----
        float acc[4] = {0.f, 0.f, 0.f, 0.f};
        const float* wrow = &W_s[tx * WSTR];
#pragma unroll
        for (int k = 0; k < DD; k += 4) {
            float4 b = *reinterpret_cast<const float4*>(&wrow[k]);
#pragma unroll
            for (int i = 0; i < 4; i++) {
                float4 a = *reinterpret_cast<const float4*>(
                               &X_s[(ty + 16 * i) * XSTR + k]);
                acc[i] = fmaf(a.x, b.x,
                         fmaf(a.y, b.y,
                         fmaf(a.z, b.z,
                         fmaf(a.w, b.w, acc[i]))));
            }
        }

        // ---- d = (xq + wq) - 2*c, exact reference expression order ----
        int   gidx = t * TM + tx;
        float wq   = g_wsq[gidx];
#pragma unroll
        for (int i = 0; i < 4; i++) {
            float d = __fsub_rn(__fadd_rn(xq[i], wq), __fmul_rn(2.0f, acc[i]));
            if (d < bv[i]) { bv[i] = d; bi[i] = gidx; }  // gidx ascending -> first-min
        }
        __syncthreads();
    }

    // ---- reduce across the 16 tx lanes (xor butterfly, half-warp local) ----
#pragma unroll
    for (int i = 0; i < 4; i++) {
        float v  = bv[i];
        int   ix = bi[i];
#pragma unroll
        for (int o = 8; o; o >>= 1) {
            float v2 = __shfl_xor_sync(0xffffffffu, v,  o);
            int   i2 = __shfl_xor_sync(0xffffffffu, ix, o);
            if (v2 < v || (v2 == v && i2 < ix)) { v = v2; ix = i2; }
        }
        if (tx == 0) {
            int n = n0 + ty + 16 * i;
            if (n < N) {
                out[2 * n]     = (float)grid[2 * ix];
                out[2 * n + 1] = (float)grid[2 * ix + 1];
            }
        }
    }
}

extern "C" void kernel_launch(void* const* d_in, const int* in_sizes, int n_in,
                              void* d_out, int out_size)
{
    // Bind by element count (robust to permutation):
    // inputs = largest (N*D), grid = smallest (M*2), weights = remaining (M*D).
    int ii = 0, ig = 0;
    for (int k = 1; k < n_in; k++) {
        if (in_sizes[k] > in_sizes[ii]) ii = k;
        if (in_sizes[k] < in_sizes[ig]) ig = k;
    }
    int iw = 0;
    for (int k = 0; k < n_in; k++) if (k != ii && k != ig) { iw = k; break; }

    const float* X    = (const float*)d_in[ii];
    const float* W    = (const float*)d_in[iw];
    const int*   grid = (const int*)d_in[ig];
    float*       out  = (float*)d_out;

    const int N = in_sizes[ii] / DD;     // 32768
    const int M = in_sizes[iw] / DD;     // 4096

    wsq_kernel<<<(M + 255) / 256, 256>>>(W, M);
    som_kernel<<<(N + TN - 1) / TN, 256>>>(X, W, grid, out, N, M);
}

// round 9
// speedup vs baseline: 1.4580x; 1.4580x over previous
#include <cuda_runtime.h>
#include <cstdint>
#include <float.h>

// SOM2D winner-take-all, GB300 sm_103a — round 9.
// d = (||x||^2 + ||w||^2) - 2*x.w ; per-distance math bitwise-identical to the
// round-5 pass. Round-8 bug: NBUF=3 ring raced (issue(it+2) lands on
// buf(it-1) while stragglers still read it). Fix: NBUF=4 ring, same syncs.
// Output written as float32 labels (harness compares floats).

#define DD      128
#define TN      32      // samples per block
#define TM      32      // units per tile
#define CH      32      // k-chunk
#define XSTR    132     // X row stride
#define WCH     36      // W chunk row stride: 36 mod 32 = 4 -> conflict-free LDS.128
#define NBUF    4       // ring depth 4: prefetch target never aliases a live reader
#define THREADS 128

__device__ float g_wsq[8192];

__global__ void wsq_kernel(const float* __restrict__ W, int M)
{
    int m = blockIdx.x * blockDim.x + threadIdx.x;
    if (m < M) {
        const float* row = W + (size_t)m * DD;
        float s = 0.f;
#pragma unroll 8
        for (int k = 0; k < DD; k++) s = fmaf(row[k], row[k], s);
        g_wsq[m] = s;
    }
}

__device__ __forceinline__ void cp16(unsigned int dst, const float* src)
{
    asm volatile("cp.async.ca.shared.global [%0], [%1], 16;\n"
                 :: "r"(dst), "l"(src));
}
__device__ __forceinline__ void cp_commit()
{
    asm volatile("cp.async.commit_group;\n" ::: "memory");
}
template<int NN> __device__ __forceinline__ void cp_wait()
{
    asm volatile("cp.async.wait_group %0;\n" :: "n"(NN) : "memory");
}

__global__ __launch_bounds__(THREADS)
void som_kernel(const float* __restrict__ X, const float* __restrict__ W,
                const int* __restrict__ grid, float* __restrict__ out,
                int N, int M)
{
    __shared__ float X_s[TN * XSTR];            // 16896 B
    __shared__ float W_s[NBUF][TM * WCH];       // 18432 B  (total 35.3 KB)

    const int tid = threadIdx.x;
    const int tx  = tid & 15;                   // unit lane
    const int ty  = tid >> 4;                   // sample lane (0..7)
    const int n0  = blockIdx.x * TN;

    const int nt    = M / TM;                   // unit tiles
    const int iters = nt * (DD / CH);           // chunk iterations

    // W-chunk fill coords for this thread (2 float4 per iter)
    const int fr0 = tid >> 3,          fc0 = tid & 7;
    const int fr1 = (tid + 128) >> 3,  fc1 = tid & 7;

    auto issue = [&](int it) {
        int t = it >> 2, c = it & 3;
        int buf = it % NBUF;
        unsigned int dbase = (unsigned int)__cvta_generic_to_shared(&W_s[buf][0]);
        int mr0 = t * TM + fr0; if (mr0 >= M) mr0 = M - 1;
        int mr1 = t * TM + fr1; if (mr1 >= M) mr1 = M - 1;
        cp16(dbase + (unsigned int)((fr0 * WCH + 4 * fc0) * 4),
             W + (size_t)mr0 * DD + c * CH + 4 * fc0);
        cp16(dbase + (unsigned int)((fr1 * WCH + 4 * fc1) * 4),
             W + (size_t)mr1 * DD + c * CH + 4 * fc1);
    };

    // prologue: start the first two W chunks
    if (iters > 0) { issue(0); cp_commit(); }
    if (iters > 1) { issue(1); cp_commit(); }

    // ---- X tile fill (float4 coalesced) ----
    for (int i = tid; i < TN * (DD / 4); i += THREADS) {
        int r = i >> 5, c4 = i & 31;
        float4 v = (n0 + r < N)
                 ? reinterpret_cast<const float4*>(X + (size_t)(n0 + r) * DD)[c4]
                 : make_float4(0.f, 0.f, 0.f, 0.f);
        *reinterpret_cast<float4*>(&X_s[r * XSTR + 4 * c4]) = v;
    }
    __syncthreads();

    // ---- per-row ||x||^2 (same scalar order as round 5) ----
    float xq[4];
#pragma unroll
    for (int i = 0; i < 4; i++) {
        const float* xr = &X_s[(ty + 8 * i) * XSTR];
        float s = 0.f;
#pragma unroll 8
        for (int k = 0; k < DD; k++) s = fmaf(xr[k], xr[k], s);
        xq[i] = s;
    }

    float bv[4];
    int   bi[4];
#pragma unroll
    for (int i = 0; i < 4; i++) { bv[i] = FLT_MAX; bi[i] = 0; }

    float acc[4][2] = {};
    float wq0 = 0.f, wq1 = 0.f;

    for (int it = 0; it < iters; it++) {
        if (it + 2 < iters) issue(it + 2);
        cp_commit();                 // one group per iter (may be empty at tail)
        cp_wait<2>();                // chunk 'it' landed (thread-local)
        __syncthreads();             // visible to all; prev compute done

        const int t   = it >> 2;
        const int c   = it & 3;
        const int buf = it % NBUF;

        if (c == 0) {                // prefetch ||w||^2 early in the tile
            wq0 = g_wsq[t * TM + tx];
            wq1 = g_wsq[t * TM + tx + 16];
        }

        const float* wr0 = &W_s[buf][tx * WCH];
        const float* wr1 = &W_s[buf][(tx + 16) * WCH];
        const int    kof = c * CH;

#pragma unroll
        for (int kk = 0; kk < CH; kk += 4) {
            float4 b0 = *reinterpret_cast<const float4*>(&wr0[kk]);
            float4 b1 = *reinterpret_cast<const float4*>(&wr1[kk]);
#pragma unroll
            for (int i = 0; i < 4; i++) {
                float4 a = *reinterpret_cast<const float4*>(
                               &X_s[(ty + 8 * i) * XSTR + kof + kk]);
                acc[i][0] = fmaf(a.x, b0.x,
                            fmaf(a.y, b0.y,
                            fmaf(a.z, b0.z,
                            fmaf(a.w, b0.w, acc[i][0]))));
                acc[i][1] = fmaf(a.x, b1.x,
                            fmaf(a.y, b1.y,
                            fmaf(a.z, b1.z,
                            fmaf(a.w, b1.w, acc[i][1]))));
            }
        }

        if (c == 3) {                // tile complete: argmin update, reset acc
#pragma unroll
            for (int i = 0; i < 4; i++) {
                float d0 = __fsub_rn(__fadd_rn(xq[i], wq0), __fmul_rn(2.0f, acc[i][0]));
                int   g0 = t * TM + tx;
                if (d0 < bv[i]) { bv[i] = d0; bi[i] = g0; }
                float d1 = __fsub_rn(__fadd_rn(xq[i], wq1), __fmul_rn(2.0f, acc[i][1]));
                int   g1 = t * TM + tx + 16;
                if (d1 < bv[i]) { bv[i] = d1; bi[i] = g1; }
                acc[i][0] = 0.f; acc[i][1] = 0.f;
            }
        }
    }
    cp_wait<0>();

    // ---- reduce across the 16 tx lanes (xor butterfly, tie -> min index) ----
#pragma unroll
    for (int i = 0; i < 4; i++) {
        float v  = bv[i];
        int   ix = bi[i];
#pragma unroll
        for (int o = 8; o; o >>= 1) {
            float v2 = __shfl_xor_sync(0xffffffffu, v,  o);
            int   i2 = __shfl_xor_sync(0xffffffffu, ix, o);
            if (v2 < v || (v2 == v && i2 < ix)) { v = v2; ix = i2; }
        }
        if (tx == 0) {
            int n = n0 + ty + 8 * i;
            if (n < N) {
                out[2 * n]     = (float)grid[2 * ix];
                out[2 * n + 1] = (float)grid[2 * ix + 1];
            }
        }
    }
}

extern "C" void kernel_launch(void* const* d_in, const int* in_sizes, int n_in,
                              void* d_out, int out_size)
{
    // Bind by element count: inputs = largest, grid = smallest, weights = rest.
    int ii = 0, ig = 0;
    for (int k = 1; k < n_in; k++) {
        if (in_sizes[k] > in_sizes[ii]) ii = k;
        if (in_sizes[k] < in_sizes[ig]) ig = k;
    }
    int iw = 0;
    for (int k = 0; k < n_in; k++) if (k != ii && k != ig) { iw = k; break; }

    const float* X    = (const float*)d_in[ii];
    const float* W    = (const float*)d_in[iw];
    const int*   grid = (const int*)d_in[ig];
    float*       out  = (float*)d_out;

    const int N = in_sizes[ii] / DD;     // 32768
    const int M = in_sizes[iw] / DD;     // 4096

    wsq_kernel<<<(M + 255) / 256, 256>>>(W, M);
    som_kernel<<<(N + TN - 1) / TN, THREADS>>>(X, W, grid, out, N, M);
}

// round 10
// speedup vs baseline: 1.7476x; 1.1986x over previous
#include <cuda_runtime.h>
#include <cstdint>
#include <float.h>

// SOM2D winner-take-all, GB300 sm_103a — round 10.
// d = (||x||^2 + ||w||^2) - 2*x.w. R9: L1=87% AND 3-reg FFMA floor ~955us both
// near-saturated. This round: packed fma.rn.f32x2 (2 FMA/instr, Blackwell-only,
// inline PTX) halves the math floor to ~477us; 8x4 thread tile + XOR-swizzled
// smem keeps LDS wavefronts under the FFMA2 demand. Exactly 48KB static smem.
// wsq math bitwise-identical to R9; cross-term k-order changes (f32x2 pairs).

#define DD      128
#define TN      64      // samples per block
#define TM      64      // units per tile
#define CH      32      // k-chunk
#define THREADS 128

__device__ float g_wsq[8192];

__global__ void wsq_kernel(const float* __restrict__ W, int M)
{
    int m = blockIdx.x * blockDim.x + threadIdx.x;
    if (m < M) {
        const float* row = W + (size_t)m * DD;
        float s = 0.f;
#pragma unroll 8
        for (int k = 0; k < DD; k++) s = fmaf(row[k], row[k], s);
        g_wsq[m] = s;
    }
}

__device__ __forceinline__ void cp16(unsigned int dst, const float* src)
{
    asm volatile("cp.async.ca.shared.global [%0], [%1], 16;\n"
                 :: "r"(dst), "l"(src));
}
__device__ __forceinline__ void cp_commit()
{
    asm volatile("cp.async.commit_group;\n" ::: "memory");
}
template<int NN> __device__ __forceinline__ void cp_wait()
{
    asm volatile("cp.async.wait_group %0;\n" :: "n"(NN) : "memory");
}
__device__ __forceinline__ void ffma2(unsigned long long& acc,
                                      unsigned long long a,
                                      unsigned long long b)
{
    asm("fma.rn.f32x2 %0, %1, %2, %0;" : "+l"(acc) : "l"(a), "l"(b));
}

__global__ __launch_bounds__(THREADS)
void som_kernel(const float* __restrict__ X, const float* __restrict__ W,
                const int* __restrict__ grid, float* __restrict__ out,
                int N, int M)
{
    __shared__ float X_s[TN * DD];       // 32768 B, quad-XOR swizzled
    __shared__ float W_s[2][TM * CH];    // 16384 B, quad-XOR swizzled
                                         // total = 49152 B (static limit)

    const int tid = threadIdx.x;
    const int tx  = tid & 15;            // unit lane
    const int ty  = tid >> 4;            // sample lane (0..7)
    const int n0  = blockIdx.x * TN;

    const int iters = (M / TM) * (DD / CH);   // 64 * 4 = 256

    // ---- W chunk fill: 4x cp.async(16B) per thread, swizzled dst ----
    auto issue = [&](int it) {
        int t = it >> 2, c = it & 3, buf = it & 1;
        unsigned int dbase = (unsigned int)__cvta_generic_to_shared(&W_s[buf][0]);
#pragma unroll
        for (int p = 0; p < 4; p++) {
            int idx = tid + THREADS * p;
            int fr  = idx >> 3;          // row 0..63
            int fc  = idx & 7;           // quad 0..7
            int mr  = t * TM + fr; if (mr >= M) mr = M - 1;
            unsigned int dst = dbase +
                (unsigned int)((fr * CH + 4 * (fc ^ (fr & 7))) * 4);
            cp16(dst, W + (size_t)mr * DD + c * CH + 4 * fc);
        }
    };

    issue(0); cp_commit();

    // ---- X tile fill [TN x DD], float4, quad-XOR swizzle (q ^= r&7) ----
    for (int i = tid; i < TN * (DD / 4); i += THREADS) {
        int r = i >> 5, c4 = i & 31;
        float4 v = (n0 + r < N)
                 ? reinterpret_cast<const float4*>(X + (size_t)(n0 + r) * DD)[c4]
                 : make_float4(0.f, 0.f, 0.f, 0.f);
        *reinterpret_cast<float4*>(&X_s[r * DD + 4 * (c4 ^ (r & 7))]) = v;
    }
    __syncthreads();

    // ---- per-sample ||x||^2 (order argmin-invariant per sample) ----
    float xq[8];
#pragma unroll
    for (int i = 0; i < 8; i++) {
        int r = ty + 8 * i;              // r & 7 == ty
        float s = 0.f;
#pragma unroll
        for (int q = 0; q < 32; q++) {
            float4 v = *reinterpret_cast<const float4*>(&X_s[r * DD + 4 * (q ^ ty)]);
            s = fmaf(v.x, v.x, s); s = fmaf(v.y, v.y, s);
            s = fmaf(v.z, v.z, s); s = fmaf(v.w, v.w, s);
        }
        xq[i] = s;
    }

    float bv[8];
    int   bi[8];
#pragma unroll
    for (int i = 0; i < 8; i++) { bv[i] = FLT_MAX; bi[i] = 0; }

    unsigned long long acc[8][4];
#pragma unroll
    for (int i = 0; i < 8; i++)
#pragma unroll
        for (int j = 0; j < 4; j++) acc[i][j] = 0ull;

    float wq[4] = {0.f, 0.f, 0.f, 0.f};

    for (int it = 0; it < iters; it++) {
        cp_wait<0>();                    // chunk 'it' landed (sole outstanding)
        __syncthreads();                 // visible to all; prev compute done
        if (it + 1 < iters) { issue(it + 1); cp_commit(); }

        const int t   = it >> 2;
        const int c   = it & 3;
        const int buf = it & 1;

        if (c == 0) {
#pragma unroll
            for (int j = 0; j < 4; j++) wq[j] = g_wsq[t * TM + tx + 16 * j];
        }

        const int txs = tx & 7;
#pragma unroll
        for (int q = 0; q < CH / 4; q++) {
            ulonglong2 b[4];
#pragma unroll
            for (int j = 0; j < 4; j++) {
                int row = tx + 16 * j;   // row & 7 == tx & 7
                b[j] = *reinterpret_cast<const ulonglong2*>(
                           &W_s[buf][row * CH + 4 * (q ^ txs)]);
            }
            const int qa = c * (CH / 4) + q;     // full k-quad 0..31
#pragma unroll
            for (int i = 0; i < 8; i++) {
                int row = ty + 8 * i;
                ulonglong2 a = *reinterpret_cast<const ulonglong2*>(
                                   &X_s[row * DD + 4 * (qa ^ ty)]);
#pragma unroll
                for (int j = 0; j < 4; j++) {
                    ffma2(acc[i][j], a.x, b[j].x);
                    ffma2(acc[i][j], a.y, b[j].y);
                }
            }
        }

        if (c == 3) {                    // tile done: argmin update, reset acc
#pragma unroll
            for (int j = 0; j < 4; j++) {
                int g = t * TM + tx + 16 * j;
#pragma unroll
                for (int i = 0; i < 8; i++) {
                    float lo = __uint_as_float((unsigned int)(acc[i][j] & 0xffffffffull));
                    float hi = __uint_as_float((unsigned int)(acc[i][j] >> 32));
                    float cr = __fadd_rn(lo, hi);
                    float d  = __fsub_rn(__fadd_rn(xq[i], wq[j]),
                                         __fmul_rn(2.0f, cr));
                    if (d < bv[i]) { bv[i] = d; bi[i] = g; }  // ascending g -> first-min
                    acc[i][j] = 0ull;
                }
            }
        }
    }

    // ---- reduce across the 16 tx lanes (xor butterfly, tie -> min index) ----
#pragma unroll
    for (int i = 0; i < 8; i++) {
        float v  = bv[i];
        int   ix = bi[i];
#pragma unroll
        for (int o = 8; o; o >>= 1) {
            float v2 = __shfl_xor_sync(0xffffffffu, v,  o);
            int   i2 = __shfl_xor_sync(0xffffffffu, ix, o);
            if (v2 < v || (v2 == v && i2 < ix)) { v = v2; ix = i2; }
        }
        if (tx == 0) {
            int n = n0 + ty + 8 * i;
            if (n < N) {
                out[2 * n]     = (float)grid[2 * ix];
                out[2 * n + 1] = (float)grid[2 * ix + 1];
            }
        }
    }
}

extern "C" void kernel_launch(void* const* d_in, const int* in_sizes, int n_in,
                              void* d_out, int out_size)
{
    // Bind by element count: inputs = largest, grid = smallest, weights = rest.
    int ii = 0, ig = 0;
    for (int k = 1; k < n_in; k++) {
        if (in_sizes[k] > in_sizes[ii]) ii = k;
        if (in_sizes[k] < in_sizes[ig]) ig = k;
    }
    int iw = 0;
    for (int k = 0; k < n_in; k++) if (k != ii && k != ig) { iw = k; break; }

    const float* X    = (const float*)d_in[ii];
    const float* W    = (const float*)d_in[iw];
    const int*   grid = (const int*)d_in[ig];
    float*       out  = (float*)d_out;

    const int N = in_sizes[ii] / DD;     // 32768
    const int M = in_sizes[iw] / DD;     // 4096

    wsq_kernel<<<(M + 255) / 256, 256>>>(W, M);
    som_kernel<<<(N + TN - 1) / TN, THREADS>>>(X, W, grid, out, N, M);
}